// round 13
// baseline (speedup 1.0000x reference)
#include <cuda_runtime.h>
#include <cstdint>

// FeaturesLoss: mma.sync m16n8k32 s8 (int32 accum) with per-row quantization,
// exact fp32 norms, persistent 128-thread CTAs (2/SM), 4-chunk cp.async ring,
// 128x128 tiles (64x64/warp), ordered-pair (j>i, x2), deterministic reduction.

#define BN    8192
#define DIM   128
#define TM    128
#define NT    (BN / TM)             // 64
#define NBLK  (NT * (NT + 1) / 2)   // 2080 upper-tri tiles
#define MARGIN 2.0f
#define NPERS (152 * 2)

#define NCHUNK 4                    // K chunks of 32 int8 (32 B per row)
#define PITCH  48                   // bytes per row per chunk (12 words)
#define PITCHW 12
#define ACH    (TM * PITCH)         // 6144
#define BCH    (TM * PITCH)         // 6144
#define SM_A   0
#define SM_B   (NCHUNK * ACH)       // 24576
#define SM_STG (SM_B + NCHUNK * BCH)// 49152
#define STGSZ  3072                 // sqI,sqJ,scI,scJ,lbI,lbJ (512 B each)
#define SM_TOT (SM_STG + 2 * STGSZ) // 55296 B per CTA (x2 = 110 KB/SM)

__device__ float      g_sq[BN];
__device__ float      g_scale[BN];           // per-row quant scale
__device__ int        g_lab[BN];
__device__ uint32_t   g_i8[BN * DIM / 4];    // packed int8 features (1 MB)
__device__ float      g_partials[NBLK];
__device__ long long  g_poscnt[NBLK];
__device__ unsigned   g_ticket;

__device__ __forceinline__ uint32_t smem_u32(const void* p) {
    uint32_t a;
    asm("{ .reg .u64 t; cvta.to.shared.u64 t, %1; cvt.u32.u64 %0, t; }" : "=r"(a) : "l"(p));
    return a;
}
__device__ __forceinline__ void cp16(uint32_t dst, const void* src) {
    asm volatile("cp.async.cg.shared.global [%0], [%1], 16;" :: "r"(dst), "l"(src));
}
__device__ __forceinline__ void cp_commit() {
    asm volatile("cp.async.commit_group;" ::: "memory");
}
template<int N> __device__ __forceinline__ void cp_wait() {
    asm volatile("cp.async.wait_group %0;" :: "n"(N) : "memory");
}
__device__ __forceinline__ void mma_s8(int c[4], uint32_t a0, uint32_t a1,
                                       uint32_t a2, uint32_t a3,
                                       uint32_t b0, uint32_t b1) {
    asm volatile(
        "mma.sync.aligned.m16n8k32.row.col.s32.s8.s8.s32 "
        "{%0,%1,%2,%3}, {%4,%5,%6,%7}, {%8,%9}, {%0,%1,%2,%3};"
        : "+r"(c[0]), "+r"(c[1]), "+r"(c[2]), "+r"(c[3])
        : "r"(a0), "r"(a1), "r"(a2), "r"(a3), "r"(b0), "r"(b1));
}
__device__ __forceinline__ void decode_tile(int idx, int& i0, int& j0) {
    int bi = 0;
    while (idx >= NT - bi) { idx -= NT - bi; bi++; }
    i0 = bi * TM;
    j0 = (bi + idx) * TM;
}

// ---------------------------------------------------------------------------
// Kernel 0: exact norms, labels (int64/int32 probe), per-row int8 quantization.
// ---------------------------------------------------------------------------
__global__ void prep_kernel(const float* __restrict__ F,
                            const void* __restrict__ labels_raw) {
    if (blockIdx.x == 0 && threadIdx.x == 0) g_ticket = 0;  // reset per replay

    int warp = (blockIdx.x * blockDim.x + threadIdx.x) >> 5;
    int lane = threadIdx.x & 31;
    if (warp >= BN) return;

    const int* w = (const int*)labels_raw;
    int probe = w[2 * lane + 1];
    unsigned is64 = __all_sync(0xffffffffu, probe == 0);

    const float4* row = (const float4*)(F + (size_t)warp * DIM);
    float4 f = row[lane];

    // exact squared norm + row max|f|
    float s  = f.x * f.x + f.y * f.y + f.z * f.z + f.w * f.w;
    float mx = fmaxf(fmaxf(fabsf(f.x), fabsf(f.y)), fmaxf(fabsf(f.z), fabsf(f.w)));
    #pragma unroll
    for (int off = 16; off; off >>= 1) {
        s  += __shfl_xor_sync(0xffffffffu, s,  off);
        mx  = fmaxf(mx, __shfl_xor_sync(0xffffffffu, mx, off));
    }

    float scale = mx * (1.0f / 127.0f);
    float inv   = 127.0f / mx;

    int q0 = (int)rintf(f.x * inv);
    int q1 = (int)rintf(f.y * inv);
    int q2 = (int)rintf(f.z * inv);
    int q3 = (int)rintf(f.w * inv);
    uint32_t packed = (uint32_t)(q0 & 0xFF) | ((uint32_t)(q1 & 0xFF) << 8)
                    | ((uint32_t)(q2 & 0xFF) << 16) | ((uint32_t)(q3 & 0xFF) << 24);
    g_i8[(size_t)warp * 32 + lane] = packed;

    if (lane == 0) {
        g_sq[warp]    = s;
        g_scale[warp] = scale;
        int lab;
        if (is64) lab = (int)((const long long*)labels_raw)[warp];
        else      lab = w[warp];
        g_lab[warp] = lab;
    }
}

// ---------------------------------------------------------------------------
// Issue cp.async for one K=32 chunk (32 B/row) of tile (i0,j0) into buffer c.
__device__ __forceinline__ void issue_chunk(uint32_t sbase, int i0, int j0,
                                            int c, int t) {
    const char* P = (const char*)g_i8;            // 128 B per feature row
    #pragma unroll
    for (int s = t; s < TM * 2; s += 128) {       // A: 256 16B segs
        int r = s >> 1, q = s & 1;
        cp16(sbase + SM_A + c * ACH + r * PITCH + q * 16,
             P + (size_t)(i0 + r) * 128 + c * 32 + q * 16);
    }
    #pragma unroll
    for (int s = t; s < TM * 2; s += 128) {       // B: 256 16B segs
        int r = s >> 1, q = s & 1;
        cp16(sbase + SM_B + c * BCH + r * PITCH + q * 16,
             P + (size_t)(j0 + r) * 128 + c * 32 + q * 16);
    }
}

// ---------------------------------------------------------------------------
__global__ void __launch_bounds__(128, 2)
tile_kernel() {
    extern __shared__ char smem[];
    uint32_t sbase = smem_u32(smem);

    int t = threadIdx.x;
    int wid = t >> 5, lane = t & 31;
    int gid = lane >> 2, tig = lane & 3;
    int wm = wid & 1, wn = wid >> 1;     // 2x2 grid of 64x64 subtiles
    int mbase = wm * 64, nbase = wn * 64;

    __shared__ int s_tick;
    __shared__ float rbuf[4];
    __shared__ int   rcnt[4];

    if (t == 0) s_tick = (int)atomicAdd(&g_ticket, 1u);
    __syncthreads();
    int cur = s_tick;
    if (cur >= NBLK) return;

    int i0, j0;
    decode_tile(cur, i0, j0);

    #pragma unroll
    for (int c = 0; c < NCHUNK; c++) {
        issue_chunk(sbase, i0, j0, c, t);
        cp_commit();
    }

    int parity = 0;
    for (;;) {
        if (t == 0) s_tick = (int)atomicAdd(&g_ticket, 1u);
        {
            char* stg = smem + SM_STG + parity * STGSZ;
            float* sqI = (float*)stg;
            float* sqJ = (float*)(stg + 512);
            float* scI = (float*)(stg + 1024);
            float* scJ = (float*)(stg + 1536);
            int*   lbI = (int*)  (stg + 2048);
            int*   lbJ = (int*)  (stg + 2560);
            sqI[t] = g_sq[i0 + t];     lbI[t] = g_lab[i0 + t];
            sqJ[t] = g_sq[j0 + t];     lbJ[t] = g_lab[j0 + t];
            scI[t] = g_scale[i0 + t];  scJ[t] = g_scale[j0 + t];
        }
        __syncthreads();
        int nxt = s_tick;
        int ni0 = 0, nj0 = 0;
        bool more = (nxt < NBLK);
        if (more) decode_tile(nxt, ni0, nj0);

        int acc[4][8][4];
        #pragma unroll
        for (int mf = 0; mf < 4; mf++)
            #pragma unroll
            for (int nf = 0; nf < 8; nf++)
                #pragma unroll
                for (int rr = 0; rr < 4; rr++) acc[mf][nf][rr] = 0;

        // ring over 4 K=32 chunks: one k32 MMA group per chunk
        #pragma unroll
        for (int c = 0; c < NCHUNK; c++) {
            cp_wait<3>();
            __syncthreads();

            const uint32_t* Ac = (const uint32_t*)(smem + SM_A + c * ACH);
            const uint32_t* Bc = (const uint32_t*)(smem + SM_B + c * BCH);

            uint32_t a[4][4];
            #pragma unroll
            for (int mf = 0; mf < 4; mf++) {
                const uint32_t* r0 = Ac + (size_t)(mbase + 16 * mf + gid) * PITCHW;
                const uint32_t* r1 = Ac + (size_t)(mbase + 16 * mf + gid + 8) * PITCHW;
                a[mf][0] = r0[tig];
                a[mf][1] = r1[tig];
                a[mf][2] = r0[tig + 4];
                a[mf][3] = r1[tig + 4];
            }
            uint32_t b[8][2];
            #pragma unroll
            for (int nf = 0; nf < 8; nf++) {
                const uint32_t* rn = Bc + (size_t)(nbase + 8 * nf + gid) * PITCHW;
                b[nf][0] = rn[tig];
                b[nf][1] = rn[tig + 4];
            }
            #pragma unroll
            for (int mf = 0; mf < 4; mf++)
                #pragma unroll
                for (int nf = 0; nf < 8; nf++)
                    mma_s8(acc[mf][nf], a[mf][0], a[mf][1], a[mf][2], a[mf][3],
                           b[nf][0], b[nf][1]);

            __syncthreads();
            if (more) issue_chunk(sbase, ni0, nj0, c, t);
            cp_commit();
        }

        // ---- fused epilogue: dequant + loss; ordered pairs gj > gi, x2 ----
        const char* stg = smem + SM_STG + parity * STGSZ;
        const float* sqI = (const float*)stg;
        const float* sqJ = (const float*)(stg + 512);
        const float* scI = (const float*)(stg + 1024);
        const float* scJ = (const float*)(stg + 1536);
        const int*   lbI = (const int*)  (stg + 2048);
        const int*   lbJ = (const int*)  (stg + 2560);

        float lsum = 0.0f;
        int   lcnt = 0;
        #pragma unroll
        for (int mf = 0; mf < 4; mf++) {
            #pragma unroll
            for (int rr = 0; rr < 2; rr++) {
                int m  = mbase + 16 * mf + gid + 8 * rr;
                int gi = i0 + m;
                float sqi = sqI[m];
                float sci = scI[m];
                int   li  = lbI[m];
                #pragma unroll
                for (int nf = 0; nf < 8; nf++) {
                    #pragma unroll
                    for (int cc = 0; cc < 2; cc++) {
                        int n  = nbase + 8 * nf + tig * 2 + cc;
                        int gj = j0 + n;
                        if (gj <= gi) continue;
                        float dot = (float)acc[mf][nf][rr * 2 + cc] * (sci * scJ[n]);
                        float d2 = fmaxf(sqi + sqJ[n] - 2.0f * dot, 0.0f);
                        if (li == lbJ[n]) {
                            lsum += d2;
                            lcnt++;
                        } else if (d2 < MARGIN * MARGIN) {   // ~never (8 sigma)
                            float h = MARGIN - sqrtf(d2);
                            lsum += h * h;
                        }
                    }
                }
            }
        }

        #pragma unroll
        for (int off = 16; off; off >>= 1) {
            lsum += __shfl_xor_sync(0xffffffffu, lsum, off);
            lcnt += __shfl_xor_sync(0xffffffffu, lcnt, off);
        }
        if (lane == 0) { rbuf[wid] = lsum; rcnt[wid] = lcnt; }
        __syncthreads();
        if (t == 0) {
            float s = 0.0f; long long c = 0;
            #pragma unroll
            for (int wd = 0; wd < 4; wd++) { s += rbuf[wd]; c += rcnt[wd]; }
            g_partials[cur] = s * 2.0f;
            g_poscnt[cur]   = c * 2LL;
        }

        if (!more) break;
        cur = nxt; i0 = ni0; j0 = nj0; parity ^= 1;
    }
}

// ---------------------------------------------------------------------------
__global__ void finalize_kernel(float* __restrict__ out) {
    int t = threadIdx.x;
    double s = 0.0; long long c = 0;
    for (int i = t; i < NBLK; i += 256) {
        s += (double)g_partials[i];
        c += g_poscnt[i];
    }
    __shared__ double    sd[256];
    __shared__ long long sc[256];
    sd[t] = s; sc[t] = c;
    __syncthreads();
    for (int off = 128; off; off >>= 1) {
        if (t < off) { sd[t] += sd[t + off]; sc[t] += sc[t + off]; }
        __syncthreads();
    }
    if (t == 0) {
        double total = sd[0];
        double denom = (double)((long long)BN * (BN - 1));
        out[0] = (float)(sc[0] > 0 ? total / denom : total);
    }
}

// ---------------------------------------------------------------------------
extern "C" void kernel_launch(void* const* d_in, const int* in_sizes, int n_in,
                              void* d_out, int out_size) {
    const float* F      = (const float*)d_in[0];
    const void*  labels = d_in[1];
    float*       out    = (float*)d_out;

    cudaFuncSetAttribute(tile_kernel,
                         cudaFuncAttributeMaxDynamicSharedMemorySize, SM_TOT);

    prep_kernel<<<BN / 8, 256>>>(F, labels);
    tile_kernel<<<NPERS, 128, SM_TOT>>>();
    finalize_kernel<<<1, 256>>>(out);
}

// round 14
// speedup vs baseline: 1.3353x; 1.3353x over previous
#include <cuda_runtime.h>
#include <cuda_fp16.h>
#include <cstdint>

// FeaturesLoss: mma.sync m16n8k16 fp16 with **fp16 accumulators** (2x rate on
// consumer-gated legacy tensor pipes), persistent 128-thread CTAs (2/SM),
// 4-chunk cp.async ring, 128x128 tiles (64x64/warp), ordered-pair (j>i, x2),
// deterministic reduction.

#define BN    8192
#define DIM   128
#define TM    128
#define NT    (BN / TM)             // 64
#define NBLK  (NT * (NT + 1) / 2)   // 2080 upper-tri tiles
#define MARGIN 2.0f
#define NPERS (152 * 2)

#define NCHUNK 4                    // K chunks of 32 (fp16: 64 B per row)
#define PITCH  80                   // bytes per row per chunk (20 words)
#define PITCHW 20
#define ACH    (TM * PITCH)         // 10240
#define BCH    (TM * PITCH)         // 10240
#define SM_A   0
#define SM_B   (NCHUNK * ACH)       // 40960
#define SM_STG (SM_B + NCHUNK * BCH)// 81920
#define STGSZ  2048                 // sqI/sqJ/lbI/lbJ (512 B each)
#define SM_TOT (SM_STG + 2 * STGSZ) // 86016 B per CTA (x2 CTAs = 172 KB/SM)

__device__ float      g_sq[BN];
__device__ int        g_lab[BN];
__device__ uint32_t   g_f16[BN * DIM / 2];   // packed half2, natural k order
__device__ float      g_partials[NBLK];
__device__ long long  g_poscnt[NBLK];
__device__ unsigned   g_ticket;

__device__ __forceinline__ uint32_t smem_u32(const void* p) {
    uint32_t a;
    asm("{ .reg .u64 t; cvta.to.shared.u64 t, %1; cvt.u32.u64 %0, t; }" : "=r"(a) : "l"(p));
    return a;
}
__device__ __forceinline__ void cp16(uint32_t dst, const void* src) {
    asm volatile("cp.async.cg.shared.global [%0], [%1], 16;" :: "r"(dst), "l"(src));
}
__device__ __forceinline__ void cp_commit() {
    asm volatile("cp.async.commit_group;" ::: "memory");
}
template<int N> __device__ __forceinline__ void cp_wait() {
    asm volatile("cp.async.wait_group %0;" :: "n"(N) : "memory");
}
// fp16 accumulate variant: D,C are 2 x b32 (4 halves)
__device__ __forceinline__ void mma_f16acc(uint32_t c[2], uint32_t a0, uint32_t a1,
                                           uint32_t a2, uint32_t a3,
                                           uint32_t b0, uint32_t b1) {
    asm volatile(
        "mma.sync.aligned.m16n8k16.row.col.f16.f16.f16.f16 "
        "{%0,%1}, {%2,%3,%4,%5}, {%6,%7}, {%0,%1};"
        : "+r"(c[0]), "+r"(c[1])
        : "r"(a0), "r"(a1), "r"(a2), "r"(a3), "r"(b0), "r"(b1));
}
__device__ __forceinline__ void decode_tile(int idx, int& i0, int& j0) {
    int bi = 0;
    while (idx >= NT - bi) { idx -= NT - bi; bi++; }
    i0 = bi * TM;
    j0 = (bi + idx) * TM;
}

// ---------------------------------------------------------------------------
// Kernel 0: norms (exact fp32), labels (int64/int32 probe), fp16 packed copy.
// ---------------------------------------------------------------------------
__global__ void prep_kernel(const float* __restrict__ F,
                            const void* __restrict__ labels_raw) {
    if (blockIdx.x == 0 && threadIdx.x == 0) g_ticket = 0;  // reset per replay

    int warp = (blockIdx.x * blockDim.x + threadIdx.x) >> 5;
    int lane = threadIdx.x & 31;
    if (warp >= BN) return;

    const int* w = (const int*)labels_raw;
    int probe = w[2 * lane + 1];
    unsigned is64 = __all_sync(0xffffffffu, probe == 0);

    const float4* row = (const float4*)(F + (size_t)warp * DIM);
    float4 f = row[lane];

    __half2 h0 = __floats2half2_rn(f.x, f.y);
    __half2 h1 = __floats2half2_rn(f.z, f.w);
    uint2 hp = { *(uint32_t*)&h0, *(uint32_t*)&h1 };
    *(uint2*)&g_f16[(size_t)warp * 64 + lane * 2] = hp;

    float s = f.x * f.x + f.y * f.y + f.z * f.z + f.w * f.w;
    #pragma unroll
    for (int off = 16; off; off >>= 1)
        s += __shfl_xor_sync(0xffffffffu, s, off);

    if (lane == 0) {
        g_sq[warp] = s;
        int lab;
        if (is64) lab = (int)((const long long*)labels_raw)[warp];
        else      lab = w[warp];
        g_lab[warp] = lab;
    }
}

// ---------------------------------------------------------------------------
// Issue cp.async for one K=32 chunk of tile (i0,j0) into ring buffer c.
__device__ __forceinline__ void issue_chunk(uint32_t sbase, int i0, int j0,
                                            int c, int t) {
    const char* P = (const char*)g_f16;           // 256 B per feature row
    #pragma unroll
    for (int s = t; s < TM * 4; s += 128) {
        int r = s >> 2, q = s & 3;
        cp16(sbase + SM_A + c * ACH + r * PITCH + q * 16,
             P + (size_t)(i0 + r) * 256 + c * 64 + q * 16);
    }
    #pragma unroll
    for (int s = t; s < TM * 4; s += 128) {
        int r = s >> 2, q = s & 3;
        cp16(sbase + SM_B + c * BCH + r * PITCH + q * 16,
             P + (size_t)(j0 + r) * 256 + c * 64 + q * 16);
    }
}

// ---------------------------------------------------------------------------
__global__ void __launch_bounds__(128, 2)
tile_kernel() {
    extern __shared__ char smem[];
    uint32_t sbase = smem_u32(smem);

    int t = threadIdx.x;
    int wid = t >> 5, lane = t & 31;
    int gid = lane >> 2, tig = lane & 3;
    int wm = wid & 1, wn = wid >> 1;     // 2x2 grid of 64x64 subtiles
    int mbase = wm * 64, nbase = wn * 64;

    __shared__ int s_tick;
    __shared__ float rbuf[4];
    __shared__ int   rcnt[4];

    if (t == 0) s_tick = (int)atomicAdd(&g_ticket, 1u);
    __syncthreads();
    int cur = s_tick;
    if (cur >= NBLK) return;

    int i0, j0;
    decode_tile(cur, i0, j0);

    #pragma unroll
    for (int c = 0; c < NCHUNK; c++) {
        issue_chunk(sbase, i0, j0, c, t);
        cp_commit();
    }

    int parity = 0;
    for (;;) {
        if (t == 0) s_tick = (int)atomicAdd(&g_ticket, 1u);
        {
            char* stg = smem + SM_STG + parity * STGSZ;
            float* sqI = (float*)stg;
            float* sqJ = (float*)(stg + 512);
            int*   lbI = (int*)  (stg + 1024);
            int*   lbJ = (int*)  (stg + 1536);
            sqI[t] = g_sq[i0 + t];  lbI[t] = g_lab[i0 + t];
            sqJ[t] = g_sq[j0 + t];  lbJ[t] = g_lab[j0 + t];
        }
        __syncthreads();
        int nxt = s_tick;
        int ni0 = 0, nj0 = 0;
        bool more = (nxt < NBLK);
        if (more) decode_tile(nxt, ni0, nj0);

        uint32_t acc[4][8][2];               // half2 accumulators
        #pragma unroll
        for (int mf = 0; mf < 4; mf++)
            #pragma unroll
            for (int nf = 0; nf < 8; nf++) {
                acc[mf][nf][0] = 0u;
                acc[mf][nf][1] = 0u;
            }

        // ring over 4 K=32 chunks: compute chunk c, refill with next tile's c
        #pragma unroll
        for (int c = 0; c < NCHUNK; c++) {
            cp_wait<3>();
            __syncthreads();

            const uint32_t* Ac = (const uint32_t*)(smem + SM_A + c * ACH);
            const uint32_t* Bc = (const uint32_t*)(smem + SM_B + c * BCH);

            #pragma unroll
            for (int g = 0; g < 2; g++) {          // 2 k16 steps per chunk
                int kb = g * 8;
                uint32_t a[4][4];
                #pragma unroll
                for (int mf = 0; mf < 4; mf++) {
                    const uint32_t* r0 = Ac + (size_t)(mbase + 16 * mf + gid) * PITCHW + kb;
                    const uint32_t* r1 = Ac + (size_t)(mbase + 16 * mf + gid + 8) * PITCHW + kb;
                    a[mf][0] = r0[tig];
                    a[mf][1] = r1[tig];
                    a[mf][2] = r0[tig + 4];
                    a[mf][3] = r1[tig + 4];
                }
                uint32_t b[8][2];
                #pragma unroll
                for (int nf = 0; nf < 8; nf++) {
                    const uint32_t* rn = Bc + (size_t)(nbase + 8 * nf + gid) * PITCHW + kb;
                    b[nf][0] = rn[tig];
                    b[nf][1] = rn[tig + 4];
                }
                #pragma unroll
                for (int mf = 0; mf < 4; mf++)
                    #pragma unroll
                    for (int nf = 0; nf < 8; nf++)
                        mma_f16acc(acc[mf][nf], a[mf][0], a[mf][1], a[mf][2], a[mf][3],
                                   b[nf][0], b[nf][1]);
            }

            __syncthreads();               // all warps done reading buffer c
            if (more) issue_chunk(sbase, ni0, nj0, c, t);
            cp_commit();                   // possibly-empty group keeps FIFO order
        }

        // ---- fused epilogue: unpack half2 accs; ordered pairs gj > gi, x2 ----
        const char* stg = smem + SM_STG + parity * STGSZ;
        const float* sqI = (const float*)stg;
        const float* sqJ = (const float*)(stg + 512);
        const int*   lbI = (const int*)  (stg + 1024);
        const int*   lbJ = (const int*)  (stg + 1536);

        float lsum = 0.0f;
        int   lcnt = 0;
        #pragma unroll
        for (int mf = 0; mf < 4; mf++) {
            #pragma unroll
            for (int rr = 0; rr < 2; rr++) {      // reg rr: rows gid + 8*rr
                int m  = mbase + 16 * mf + gid + 8 * rr;
                int gi = i0 + m;
                float sqi = sqI[m];
                int   li  = lbI[m];
                #pragma unroll
                for (int nf = 0; nf < 8; nf++) {
                    uint32_t reg = acc[mf][nf][rr];
                    float2 dv = __half22float2(*(__half2*)&reg);
                    #pragma unroll
                    for (int cc = 0; cc < 2; cc++) {
                        int n  = nbase + 8 * nf + tig * 2 + cc;
                        int gj = j0 + n;
                        if (gj <= gi) continue;
                        float dot = cc ? dv.y : dv.x;
                        float d2 = fmaxf(sqi + sqJ[n] - 2.0f * dot, 0.0f);
                        if (li == lbJ[n]) {
                            lsum += d2;
                            lcnt++;
                        } else if (d2 < MARGIN * MARGIN) {   // ~never (8 sigma)
                            float h = MARGIN - sqrtf(d2);
                            lsum += h * h;
                        }
                    }
                }
            }
        }

        #pragma unroll
        for (int off = 16; off; off >>= 1) {
            lsum += __shfl_xor_sync(0xffffffffu, lsum, off);
            lcnt += __shfl_xor_sync(0xffffffffu, lcnt, off);
        }
        if (lane == 0) { rbuf[wid] = lsum; rcnt[wid] = lcnt; }
        __syncthreads();
        if (t == 0) {
            float s = 0.0f; long long c = 0;
            #pragma unroll
            for (int wd = 0; wd < 4; wd++) { s += rbuf[wd]; c += rcnt[wd]; }
            g_partials[cur] = s * 2.0f;
            g_poscnt[cur]   = c * 2LL;
        }

        if (!more) break;
        cur = nxt; i0 = ni0; j0 = nj0; parity ^= 1;
    }
}

// ---------------------------------------------------------------------------
__global__ void finalize_kernel(float* __restrict__ out) {
    int t = threadIdx.x;
    double s = 0.0; long long c = 0;
    for (int i = t; i < NBLK; i += 256) {
        s += (double)g_partials[i];
        c += g_poscnt[i];
    }
    __shared__ double    sd[256];
    __shared__ long long sc[256];
    sd[t] = s; sc[t] = c;
    __syncthreads();
    for (int off = 128; off; off >>= 1) {
        if (t < off) { sd[t] += sd[t + off]; sc[t] += sc[t + off]; }
        __syncthreads();
    }
    if (t == 0) {
        double total = sd[0];
        double denom = (double)((long long)BN * (BN - 1));
        out[0] = (float)(sc[0] > 0 ? total / denom : total);
    }
}

// ---------------------------------------------------------------------------
extern "C" void kernel_launch(void* const* d_in, const int* in_sizes, int n_in,
                              void* d_out, int out_size) {
    const float* F      = (const float*)d_in[0];
    const void*  labels = d_in[1];
    float*       out    = (float*)d_out;

    cudaFuncSetAttribute(tile_kernel,
                         cudaFuncAttributeMaxDynamicSharedMemorySize, SM_TOT);

    prep_kernel<<<BN / 8, 256>>>(F, labels);
    tile_kernel<<<NPERS, 128, SM_TOT>>>();
    finalize_kernel<<<1, 256>>>(out);
}